// round 3
// baseline (speedup 1.0000x reference)
#include <cuda_runtime.h>
#include <math.h>

#define Nn   8192
#define Mm   2048
#define Dd   32
#define KK   64          // stacked feature depth
#define BN   128         // samples per block tile
#define BM   128         // means per block tile
#define MB   (Mm / BM)   // 16 m-blocks
#define NB   (Nn / BN)   // 64 n-blocks
#define SSTR 132         // smem row stride in floats (33 float4)
#define SMEM_BYTES ((2 * KK * SSTR + BM) * sizeof(float))

// Scratch (device globals; no allocation allowed)
__device__ __align__(16) float g_Bfeat[Mm * KK];   // [M][64]: k<32 -> mean/std, k>=32 -> -0.5/std
__device__ __align__(16) float g_c[Mm];            // -0.5 * sum_d mean^2/std
__device__ __align__(16) float g_partial[MB * Nn]; // per-mblock partial exp-sums
__device__ __align__(16) float g_dist[Nn];

// ---------------------------------------------------------------------------
// Prep: build B-features and bias c[m]. One warp per mean (D == 32 lanes).
// ---------------------------------------------------------------------------
__global__ void prep_b_kernel(const float* __restrict__ means,
                              const float* __restrict__ stds) {
    int idx = blockIdx.x * blockDim.x + threadIdx.x;  // 0 .. M*D-1
    int m = idx >> 5;
    int d = idx & 31;
    float mean = means[m * Dd + d];
    float inv  = 1.0f / stds[m * Dd + d];
    float f1 = mean * inv;
    g_Bfeat[m * KK + d]      = f1;
    g_Bfeat[m * KK + 32 + d] = -0.5f * inv;
    float cpart = -0.5f * mean * f1;
#pragma unroll
    for (int o = 16; o > 0; o >>= 1)
        cpart += __shfl_xor_sync(0xffffffffu, cpart, o);
    if (d == 0) g_c[m] = cpart;
}

// ---------------------------------------------------------------------------
// Main: 128x128 tile GEMM (K=64) + exp epilogue + in-block m-reduction.
// gridDim.x = n-block, gridDim.y = m-block. 256 threads, 8x8 per thread.
// ---------------------------------------------------------------------------
__global__ void __launch_bounds__(256, 2)
kde_main_kernel(const float* __restrict__ samples) {
    extern __shared__ float smem[];
    float* As = smem;                 // [64][SSTR]
    float* Bs = smem + KK * SSTR;     // [64][SSTR]
    float* cs = Bs + KK * SSTR;       // [128]

    const int tid = threadIdx.x;
    const int tx = tid & 15;          // m-fragment selector
    const int ty = tid >> 4;          // n-fragment selector
    const int n0 = blockIdx.x * BN;
    const int m0 = blockIdx.y * BM;

    // --- Load A tile: samples[n0..n0+127][0..31] -> As[d][n], As[d+32][n]=s^2
    {
        const float4* s4 = (const float4*)(samples + n0 * Dd);
#pragma unroll
        for (int it = 0; it < 4; it++) {
            int fid = tid + it * 256;          // 0..1023
            int n = fid >> 3;
            int d4 = (fid & 7) * 4;
            float4 v = s4[fid];
            float vv[4] = {v.x, v.y, v.z, v.w};
#pragma unroll
            for (int j = 0; j < 4; j++) {
                int d = d4 + j;
                As[d * SSTR + n] = vv[j];
                As[(d + 32) * SSTR + n] = vv[j] * vv[j];
            }
        }
    }
    // --- Load B tile: g_Bfeat[m0..m0+127][0..63] -> Bs[k][m]
    {
        const float4* b4 = (const float4*)(g_Bfeat + m0 * KK);
#pragma unroll
        for (int it = 0; it < 8; it++) {
            int fid = tid + it * 256;          // 0..2047
            int m = fid >> 4;
            int k4 = (fid & 15) * 4;
            float4 v = b4[fid];
            float vv[4] = {v.x, v.y, v.z, v.w};
#pragma unroll
            for (int j = 0; j < 4; j++)
                Bs[(k4 + j) * SSTR + m] = vv[j];
        }
    }
    if (tid < BM) cs[tid] = g_c[m0 + tid];
    __syncthreads();

    // --- Mainloop: acc[i][j] over K=64
    float acc[8][8];
#pragma unroll
    for (int i = 0; i < 8; i++)
#pragma unroll
        for (int j = 0; j < 8; j++) acc[i][j] = 0.0f;

    const float4* As4 = (const float4*)As;
    const float4* Bs4 = (const float4*)Bs;

#pragma unroll 8
    for (int k = 0; k < KK; k++) {
        int rb = k * (SSTR / 4);
        float4 a0 = As4[rb + ty];          // n = ty*4 + 0..3
        float4 a1 = As4[rb + 16 + ty];     // n = 64 + ty*4 + 0..3
        float4 b0 = Bs4[rb + tx];          // m = tx*4 + 0..3
        float4 b1 = Bs4[rb + 16 + tx];     // m = 64 + tx*4 + 0..3
        float av[8] = {a0.x, a0.y, a0.z, a0.w, a1.x, a1.y, a1.z, a1.w};
        float bv[8] = {b0.x, b0.y, b0.z, b0.w, b1.x, b1.y, b1.z, b1.w};
#pragma unroll
        for (int i = 0; i < 8; i++)
#pragma unroll
            for (int j = 0; j < 8; j++)
                acc[i][j] = fmaf(av[i], bv[j], acc[i][j]);
    }

    // --- Epilogue: logp = acc + c[m]; p = exp(logp); sum over m
    float cj[8];
#pragma unroll
    for (int j = 0; j < 8; j++) {
        int ml = (j < 4) ? (tx * 4 + j) : (64 + tx * 4 + (j - 4));
        cj[j] = cs[ml];
    }
    float nsum[8];
#pragma unroll
    for (int i = 0; i < 8; i++) {
        float s = 0.0f;
#pragma unroll
        for (int j = 0; j < 8; j++)
            s += __expf(acc[i][j] + cj[j]);
        nsum[i] = s;
    }
    // Reduce over tx (16 lanes within each half-warp)
#pragma unroll
    for (int o = 1; o < 16; o <<= 1) {
#pragma unroll
        for (int i = 0; i < 8; i++)
            nsum[i] += __shfl_xor_sync(0xffffffffu, nsum[i], o);
    }
    if (tx == 0) {
#pragma unroll
        for (int i = 0; i < 8; i++) {
            int nl = (i < 4) ? (ty * 4 + i) : (64 + ty * 4 + (i - 4));
            g_partial[blockIdx.y * Nn + n0 + nl] = nsum[i];
        }
    }
}

// ---------------------------------------------------------------------------
// dist[n] = (1/M) * sum_mb partial[mb][n]
// ---------------------------------------------------------------------------
__global__ void dist_kernel() {
    int n = blockIdx.x * blockDim.x + threadIdx.x;
    float s = 0.0f;
#pragma unroll
    for (int mb = 0; mb < MB; mb++)
        s += g_partial[mb * Nn + n];
    g_dist[n] = s * (1.0f / (float)Mm);
}

// ---------------------------------------------------------------------------
// Single block: global max/min of dist, then out[n] = (max+min) - dist[n]
// ---------------------------------------------------------------------------
__global__ void flip_kernel(float* __restrict__ out) {
    __shared__ float smx[32], smn[32];
    int tid = threadIdx.x;             // 1024 threads
    float vals[8];
    float mx = -INFINITY, mn = INFINITY;
#pragma unroll
    for (int r = 0; r < 8; r++) {
        float v = g_dist[tid + r * 1024];
        vals[r] = v;
        mx = fmaxf(mx, v);
        mn = fminf(mn, v);
    }
#pragma unroll
    for (int o = 16; o > 0; o >>= 1) {
        mx = fmaxf(mx, __shfl_xor_sync(0xffffffffu, mx, o));
        mn = fminf(mn, __shfl_xor_sync(0xffffffffu, mn, o));
    }
    if ((tid & 31) == 0) { smx[tid >> 5] = mx; smn[tid >> 5] = mn; }
    __syncthreads();
    if (tid < 32) {
        mx = smx[tid]; mn = smn[tid];
#pragma unroll
        for (int o = 16; o > 0; o >>= 1) {
            mx = fmaxf(mx, __shfl_xor_sync(0xffffffffu, mx, o));
            mn = fminf(mn, __shfl_xor_sync(0xffffffffu, mn, o));
        }
        if (tid == 0) { smx[0] = mx; smn[0] = mn; }
    }
    __syncthreads();
    float off = smx[0] + smn[0];
#pragma unroll
    for (int r = 0; r < 8; r++)
        out[tid + r * 1024] = off - vals[r];
}

// ---------------------------------------------------------------------------
extern "C" void kernel_launch(void* const* d_in, const int* in_sizes, int n_in,
                              void* d_out, int out_size) {
    const float* samples = (const float*)d_in[0];
    const float* means   = (const float*)d_in[1];
    const float* stds    = (const float*)d_in[2];
    float* out = (float*)d_out;

    cudaFuncSetAttribute(kde_main_kernel,
                         cudaFuncAttributeMaxDynamicSharedMemorySize,
                         (int)SMEM_BYTES);

    prep_b_kernel<<<(Mm * Dd) / 256, 256>>>(means, stds);
    dim3 grid(NB, MB);
    kde_main_kernel<<<grid, 256, SMEM_BYTES>>>(samples);
    dist_kernel<<<Nn / 256, 256>>>();
    flip_kernel<<<1, 1024>>>(out);
}

// round 5
// speedup vs baseline: 1.9753x; 1.9753x over previous
#include <cuda_runtime.h>
#include <cuda_bf16.h>
#include <math.h>
#include <stdint.h>

#define Nn 8192
#define Mm 2048
#define Dd 32
#define KSTEPS 12               // K = 192 (3-product bf16 split), k16 per mma
#define STILES (Nn / 16)        // 512 sample tiles (m16)
#define MTILES (Mm / 8)         // 256 mean tiles (n8)
#define MB 16                   // mean blocks of 128

// Fragment-layout operand arrays + scratch (no allocation allowed)
__device__ __align__(16) uint32_t g_Afrag[STILES * KSTEPS * 32 * 4]; // uint4/slot
__device__ __align__(16) uint32_t g_Bfrag[MTILES * KSTEPS * 32 * 2]; // uint2/slot
__device__ __align__(16) float g_c[Mm];
__device__ __align__(16) float g_partial[MB * Nn];
__device__ __align__(16) float g_dist[Nn];
__device__ float2 g_mm[64];

// ---------------------------------------------------------------------------
__device__ __forceinline__ uint32_t pk(__nv_bfloat16 lo, __nv_bfloat16 hi) {
    __nv_bfloat162 p = __halves2bfloat162(lo, hi);  // .x = low half
    return *reinterpret_cast<uint32_t*>(&p);
}

// A-value: kb in 0..63 (k<32 -> s_d, else s_d^2); kt: 0,1 -> hi, 2 -> lo
__device__ __forceinline__ __nv_bfloat16 aval(const float* __restrict__ samples,
                                              int row, int kb, int kt) {
    int d = kb & 31;
    float x = __ldg(samples + row * Dd + d);
    float f = (kb < 32) ? x : x * x;
    __nv_bfloat16 h = __float2bfloat16(f);
    if (kt < 2) return h;
    return __float2bfloat16(f - __bfloat162float(h));
}

// B-value: kb<32 -> mean/std, else -0.5/std; kt: 0,2 -> hi, 1 -> lo
__device__ __forceinline__ __nv_bfloat16 bval(const float* __restrict__ means,
                                              const float* __restrict__ stds,
                                              int m, int kb, int kt) {
    int d = kb & 31;
    float inv = 1.0f / __ldg(stds + m * Dd + d);
    float f = (kb < 32) ? __ldg(means + m * Dd + d) * inv : -0.5f * inv;
    __nv_bfloat16 h = __float2bfloat16(f);
    if (kt != 1) return h;
    return __float2bfloat16(f - __bfloat162float(h));
}

// ---------------------------------------------------------------------------
// Fused prep: blocks [0,768) build A-frags, [768,1152) B-frags, [1152,1408) c.
// ---------------------------------------------------------------------------
__global__ void prep_kernel(const float* __restrict__ samples,
                            const float* __restrict__ means,
                            const float* __restrict__ stds) {
    int bid = blockIdx.x, tid = threadIdx.x;
    if (bid < 768) {
        // A fragments: slot = (stile*12 + ks)*32 + lane
        int gt = bid * 256 + tid;
        int lane = gt & 31, sk = gt >> 5;
        int ks = sk % KSTEPS, stile = sk / KSTEPS;
        int g = lane >> 2, t = lane & 3;
        int kt = ks >> 2;              // which of the 3 K-products
        int kb0 = (ks & 3) * 16;       // base k within 64-feature block
        int r0 = stile * 16 + g, r1 = r0 + 8;
        int k0 = kb0 + 2 * t, k1 = k0 + 1, k2 = k0 + 8, k3 = k2 + 1;
        uint4 v;
        v.x = pk(aval(samples, r0, k0, kt), aval(samples, r0, k1, kt));
        v.y = pk(aval(samples, r1, k0, kt), aval(samples, r1, k1, kt));
        v.z = pk(aval(samples, r0, k2, kt), aval(samples, r0, k3, kt));
        v.w = pk(aval(samples, r1, k2, kt), aval(samples, r1, k3, kt));
        ((uint4*)g_Afrag)[gt] = v;
    } else if (bid < 1152) {
        // B fragments: slot = (mtile*12 + ks)*32 + lane
        int gt = (bid - 768) * 256 + tid;
        int lane = gt & 31, sk = gt >> 5;
        int ks = sk % KSTEPS, mtile = sk / KSTEPS;
        int g = lane >> 2, t = lane & 3;
        int kt = ks >> 2;
        int kb0 = (ks & 3) * 16;
        int m = mtile * 8 + g;
        int k0 = kb0 + 2 * t, k1 = k0 + 1, k2 = k0 + 8, k3 = k2 + 1;
        uint2 v;
        v.x = pk(bval(means, stds, m, k0, kt), bval(means, stds, m, k1, kt));
        v.y = pk(bval(means, stds, m, k2, kt), bval(means, stds, m, k3, kt));
        ((uint2*)g_Bfrag)[gt] = v;
    } else {
        // bias c[m] = -0.5 * sum_d mean^2/std  (one warp per mean)
        int idx = (bid - 1152) * 256 + tid;
        int m = idx >> 5, d = idx & 31;
        float mean = __ldg(means + m * Dd + d);
        float inv = 1.0f / __ldg(stds + m * Dd + d);
        float cp = -0.5f * mean * mean * inv;
#pragma unroll
        for (int o = 16; o > 0; o >>= 1)
            cp += __shfl_xor_sync(0xffffffffu, cp, o);
        if (d == 0) g_c[m] = cp;
    }
}

// ---------------------------------------------------------------------------
__device__ __forceinline__ void mma16816(float* d, const uint4& a, const uint2& b) {
    asm volatile(
        "mma.sync.aligned.m16n8k16.row.col.f32.bf16.bf16.f32 "
        "{%0,%1,%2,%3}, {%4,%5,%6,%7}, {%8,%9}, {%0,%1,%2,%3};"
        : "+f"(d[0]), "+f"(d[1]), "+f"(d[2]), "+f"(d[3])
        : "r"(a.x), "r"(a.y), "r"(a.z), "r"(a.w), "r"(b.x), "r"(b.y));
}

// ---------------------------------------------------------------------------
// Main: block = 128 samples x 128 means. 8 warps = 2 (samples) x 4 (means).
// Warp tile = 64 samples x 32 means = 4 m16-tiles x 4 n8-tiles.
// ---------------------------------------------------------------------------
__global__ void __launch_bounds__(256, 2) kde_main() {
    __shared__ float spart[4][128];
    const int tid = threadIdx.x, lane = tid & 31, w = tid >> 5;
    const int wn = w >> 2, wm = w & 3, g = lane >> 2, t = lane & 3;
    const int bx = blockIdx.x, by = blockIdx.y;

    float acc[4][4][4];
#pragma unroll
    for (int mi = 0; mi < 4; mi++)
#pragma unroll
        for (int ni = 0; ni < 4; ni++)
#pragma unroll
            for (int e = 0; e < 4; e++) acc[mi][ni][e] = 0.0f;

    const uint4* __restrict__ Af = (const uint4*)g_Afrag;
    const uint2* __restrict__ Bf = (const uint2*)g_Bfrag;
    const int abase = (bx * 8 + wn * 4) * KSTEPS * 32 + lane;   // + mi*384 + ks*32
    const int bbase = (by * 16 + wm * 4) * KSTEPS * 32 + lane;  // + ni*384 + ks*32

#pragma unroll
    for (int ks = 0; ks < KSTEPS; ks++) {
        uint4 a[4];
        uint2 b[4];
#pragma unroll
        for (int mi = 0; mi < 4; mi++) a[mi] = __ldg(Af + abase + mi * 384 + ks * 32);
#pragma unroll
        for (int ni = 0; ni < 4; ni++) b[ni] = __ldg(Bf + bbase + ni * 384 + ks * 32);
#pragma unroll
        for (int mi = 0; mi < 4; mi++)
#pragma unroll
            for (int ni = 0; ni < 4; ni++)
                mma16816(acc[mi][ni], a[mi], b[ni]);
    }

    // Epilogue: logp = acc + c[col]; exp; sum over this warp's 32 mean-cols.
    const int mcol = by * 128 + wm * 32 + 2 * t;   // + ni*8, cols 2t,2t+1
#pragma unroll
    for (int mi = 0; mi < 4; mi++) {
        float s0 = 0.0f, s1 = 0.0f;
#pragma unroll
        for (int ni = 0; ni < 4; ni++) {
            float2 c = *(const float2*)(g_c + mcol + ni * 8);
            s0 += __expf(acc[mi][ni][0] + c.x) + __expf(acc[mi][ni][1] + c.y);
            s1 += __expf(acc[mi][ni][2] + c.x) + __expf(acc[mi][ni][3] + c.y);
        }
        s0 += __shfl_xor_sync(0xffffffffu, s0, 1);
        s0 += __shfl_xor_sync(0xffffffffu, s0, 2);
        s1 += __shfl_xor_sync(0xffffffffu, s1, 1);
        s1 += __shfl_xor_sync(0xffffffffu, s1, 2);
        if (t == 0) {
            spart[wm][wn * 64 + mi * 16 + g]     = s0;
            spart[wm][wn * 64 + mi * 16 + 8 + g] = s1;
        }
    }
    __syncthreads();
    if (tid < 128) {
        float v = spart[0][tid] + spart[1][tid] + spart[2][tid] + spart[3][tid];
        g_partial[by * Nn + bx * 128 + tid] = v;
    }
}

// ---------------------------------------------------------------------------
// tail1: dist[n] = mean over 16 partials; per-block (128 n) min/max -> g_mm
// ---------------------------------------------------------------------------
__global__ void tail1_kernel() {
    __shared__ float smx[4], smn[4];
    int n = blockIdx.x * 128 + threadIdx.x;
    float s = 0.0f;
#pragma unroll
    for (int mb = 0; mb < MB; mb++) s += g_partial[mb * Nn + n];
    float d = s * (1.0f / (float)Mm);
    g_dist[n] = d;
    float mx = d, mn = d;
#pragma unroll
    for (int o = 16; o > 0; o >>= 1) {
        mx = fmaxf(mx, __shfl_xor_sync(0xffffffffu, mx, o));
        mn = fminf(mn, __shfl_xor_sync(0xffffffffu, mn, o));
    }
    int wi = threadIdx.x >> 5;
    if ((threadIdx.x & 31) == 0) { smx[wi] = mx; smn[wi] = mn; }
    __syncthreads();
    if (threadIdx.x == 0) {
        mx = fmaxf(fmaxf(smx[0], smx[1]), fmaxf(smx[2], smx[3]));
        mn = fminf(fminf(smn[0], smn[1]), fminf(smn[2], smn[3]));
        g_mm[blockIdx.x] = make_float2(mx, mn);
    }
}

// ---------------------------------------------------------------------------
// tail2: global min/max over 64 block results; out = (max+min) - dist
// ---------------------------------------------------------------------------
__global__ void tail2_kernel(float* __restrict__ out) {
    __shared__ float sx[2], sn[2];
    int tid = threadIdx.x;
    if (tid < 64) {
        float2 v = g_mm[tid];
        float mx = v.x, mn = v.y;
#pragma unroll
        for (int o = 16; o > 0; o >>= 1) {
            mx = fmaxf(mx, __shfl_xor_sync(0xffffffffu, mx, o));
            mn = fminf(mn, __shfl_xor_sync(0xffffffffu, mn, o));
        }
        if ((tid & 31) == 0) { sx[tid >> 5] = mx; sn[tid >> 5] = mn; }
    }
    __syncthreads();
    float off = fmaxf(sx[0], sx[1]) + fminf(sn[0], sn[1]);
    int n = blockIdx.x * 128 + tid;
    out[n] = off - g_dist[n];
}

// ---------------------------------------------------------------------------
extern "C" void kernel_launch(void* const* d_in, const int* in_sizes, int n_in,
                              void* d_out, int out_size) {
    const float* samples = (const float*)d_in[0];
    const float* means   = (const float*)d_in[1];
    const float* stds    = (const float*)d_in[2];
    float* out = (float*)d_out;

    prep_kernel<<<1408, 256>>>(samples, means, stds);
    dim3 grid(Nn / 128, Mm / 128);
    kde_main<<<grid, 256>>>();
    tail1_kernel<<<Nn / 128, 128>>>();
    tail2_kernel<<<Nn / 128, 128>>>(out);
}

// round 7
// speedup vs baseline: 2.1310x; 1.0788x over previous
#include <cuda_runtime.h>
#include <cuda_bf16.h>
#include <math.h>
#include <stdint.h>

#define Nn 8192
#define Mm 2048
#define Dd 32
#define STILES (Nn / 16)        // 512 sample tiles (m16)
#define MTILES (Mm / 8)         // 256 mean tiles (n8)
#define KSLOTS 8                // 4 hi + 4 lo k16-groups (dedup'd)
#define MB 16                   // mean blocks of 128

// Fragment-layout operands + scratch
__device__ __align__(16) uint32_t g_Afrag[STILES * KSLOTS * 32 * 4]; // uint4/slot
__device__ __align__(16) uint32_t g_Bfrag[MTILES * KSLOTS * 32 * 2]; // uint2/slot
__device__ __align__(16) float g_c[Mm];
__device__ __align__(16) float g_partial[Nn * MB];   // [n][mb] transposed
__device__ __align__(16) float g_dist[Nn];
__device__ float2 g_mm[16];

// ---------------------------------------------------------------------------
__device__ __forceinline__ uint32_t pk(__nv_bfloat16 lo, __nv_bfloat16 hi) {
    __nv_bfloat162 p = __halves2bfloat162(lo, hi);
    return *reinterpret_cast<uint32_t*>(&p);
}
__device__ __forceinline__ __nv_bfloat16 cv(float f, bool hi) {
    __nv_bfloat16 h = __float2bfloat16(f);
    if (hi) return h;
    return __float2bfloat16(f - __bfloat162float(h));
}

// ---------------------------------------------------------------------------
// prep: blocks [0,512) A-frags, [512,768) B-frags, [768,1024) bias c.
// A slot layout: (stile, kslot) kslot 0..3 = hi(k16 group), 4..7 = lo.
// ---------------------------------------------------------------------------
__global__ void prep_kernel(const float* __restrict__ samples,
                            const float* __restrict__ means,
                            const float* __restrict__ stds) {
    int bid = blockIdx.x, tid = threadIdx.x;
    if (bid < 512) {
        int gt = bid * 256 + tid;                 // 0 .. 131071
        int lane = gt & 31, slot = gt >> 5;
        int kslot = slot & 7, stile = slot >> 3;
        int g = lane >> 2, t = lane & 3;
        bool hi = kslot < 4;
        int kb0 = (kslot & 3) * 16;               // 0,16,32,48
        bool sq = kb0 >= 32;
        int dbase = (kb0 & 16) + 2 * t;
        int r0 = stile * 16 + g, r1 = r0 + 8;
        float2 p00 = __ldg((const float2*)(samples + r0 * Dd + dbase));
        float2 p01 = __ldg((const float2*)(samples + r0 * Dd + dbase + 8));
        float2 p10 = __ldg((const float2*)(samples + r1 * Dd + dbase));
        float2 p11 = __ldg((const float2*)(samples + r1 * Dd + dbase + 8));
        if (sq) {
            p00.x *= p00.x; p00.y *= p00.y; p01.x *= p01.x; p01.y *= p01.y;
            p10.x *= p10.x; p10.y *= p10.y; p11.x *= p11.x; p11.y *= p11.y;
        }
        uint4 v;
        v.x = pk(cv(p00.x, hi), cv(p00.y, hi));
        v.y = pk(cv(p10.x, hi), cv(p10.y, hi));
        v.z = pk(cv(p01.x, hi), cv(p01.y, hi));
        v.w = pk(cv(p11.x, hi), cv(p11.y, hi));
        ((uint4*)g_Afrag)[gt] = v;
    } else if (bid < 768) {
        int gt = (bid - 512) * 256 + tid;         // 0 .. 65535
        int lane = gt & 31, slot = gt >> 5;
        int kslot = slot & 7, mtile = slot >> 3;
        int g = lane >> 2, t = lane & 3;
        bool hi = kslot < 4;
        int kb0 = (kslot & 3) * 16;
        bool isq = kb0 >= 32;
        int dbase = (kb0 & 16) + 2 * t;
        int m = mtile * 8 + g;
        float2 s0 = __ldg((const float2*)(stds + m * Dd + dbase));
        float2 s1 = __ldg((const float2*)(stds + m * Dd + dbase + 8));
        float2 f0, f1;
        if (isq) {
            f0.x = -0.5f / s0.x; f0.y = -0.5f / s0.y;
            f1.x = -0.5f / s1.x; f1.y = -0.5f / s1.y;
        } else {
            float2 m0 = __ldg((const float2*)(means + m * Dd + dbase));
            float2 m1 = __ldg((const float2*)(means + m * Dd + dbase + 8));
            f0.x = m0.x / s0.x; f0.y = m0.y / s0.y;
            f1.x = m1.x / s1.x; f1.y = m1.y / s1.y;
        }
        uint2 v;
        v.x = pk(cv(f0.x, hi), cv(f0.y, hi));
        v.y = pk(cv(f1.x, hi), cv(f1.y, hi));
        ((uint2*)g_Bfrag)[gt] = v;
    } else {
        int idx = (bid - 768) * 256 + tid;        // M*D
        int m = idx >> 5, d = idx & 31;
        float mean = __ldg(means + m * Dd + d);
        float cp = -0.5f * mean * mean / __ldg(stds + m * Dd + d);
#pragma unroll
        for (int o = 16; o > 0; o >>= 1)
            cp += __shfl_xor_sync(0xffffffffu, cp, o);
        if (d == 0) g_c[m] = cp;
    }
}

// ---------------------------------------------------------------------------
__device__ __forceinline__ void mma16816(float* d, const uint4& a, const uint2& b) {
    asm volatile(
        "mma.sync.aligned.m16n8k16.row.col.f32.bf16.bf16.f32 "
        "{%0,%1,%2,%3}, {%4,%5,%6,%7}, {%8,%9}, {%0,%1,%2,%3};"
        : "+f"(d[0]), "+f"(d[1]), "+f"(d[2]), "+f"(d[3])
        : "r"(a.x), "r"(a.y), "r"(a.z), "r"(a.w), "r"(b.x), "r"(b.y));
}

// ---------------------------------------------------------------------------
// Main: block = 128 samples x 128 means; 8 warps = 2(n) x 4(m); warp 64x32.
// Per k16-group: 3 products ah*bh + ah*bl + al*bh with register reuse.
// ---------------------------------------------------------------------------
__global__ void __launch_bounds__(256, 2) kde_main() {
    __shared__ float spart[4][128];
    const int tid = threadIdx.x, lane = tid & 31, w = tid >> 5;
    const int wn = w >> 2, wm = w & 3, g = lane >> 2, t = lane & 3;
    const int bx = blockIdx.x, by = blockIdx.y;

    float acc[4][4][4];
#pragma unroll
    for (int mi = 0; mi < 4; mi++)
#pragma unroll
        for (int ni = 0; ni < 4; ni++)
#pragma unroll
            for (int e = 0; e < 4; e++) acc[mi][ni][e] = 0.0f;

    const uint4* __restrict__ Af = (const uint4*)g_Afrag;
    const uint2* __restrict__ Bf = (const uint2*)g_Bfrag;
    const int abase = (bx * 8 + wn * 4) * KSLOTS * 32 + lane;   // + mi*256 + ks*32
    const int bbase = (by * 16 + wm * 4) * KSLOTS * 32 + lane;  // + ni*256 + ks*32

#pragma unroll
    for (int ks = 0; ks < 4; ks++) {
        uint4 ah[4];
        uint2 bh[4], bl[4];
#pragma unroll
        for (int mi = 0; mi < 4; mi++)
            ah[mi] = __ldg(Af + abase + mi * 256 + ks * 32);
#pragma unroll
        for (int ni = 0; ni < 4; ni++) {
            bh[ni] = __ldg(Bf + bbase + ni * 256 + ks * 32);
            bl[ni] = __ldg(Bf + bbase + ni * 256 + (ks + 4) * 32);
        }
#pragma unroll
        for (int mi = 0; mi < 4; mi++)
#pragma unroll
            for (int ni = 0; ni < 4; ni++)
                mma16816(acc[mi][ni], ah[mi], bh[ni]);
#pragma unroll
        for (int mi = 0; mi < 4; mi++)
#pragma unroll
            for (int ni = 0; ni < 4; ni++)
                mma16816(acc[mi][ni], ah[mi], bl[ni]);
        uint4 al[4];
#pragma unroll
        for (int mi = 0; mi < 4; mi++)
            al[mi] = __ldg(Af + abase + mi * 256 + (ks + 4) * 32);
#pragma unroll
        for (int mi = 0; mi < 4; mi++)
#pragma unroll
            for (int ni = 0; ni < 4; ni++)
                mma16816(acc[mi][ni], al[mi], bh[ni]);
    }

    // Epilogue: exp(acc + c) and sum over this warp's 32 mean columns.
    const int mcol = by * 128 + wm * 32 + 2 * t;
#pragma unroll
    for (int mi = 0; mi < 4; mi++) {
        float s0 = 0.0f, s1 = 0.0f;
#pragma unroll
        for (int ni = 0; ni < 4; ni++) {
            float2 c = *(const float2*)(g_c + mcol + ni * 8);
            s0 += __expf(acc[mi][ni][0] + c.x) + __expf(acc[mi][ni][1] + c.y);
            s1 += __expf(acc[mi][ni][2] + c.x) + __expf(acc[mi][ni][3] + c.y);
        }
        s0 += __shfl_xor_sync(0xffffffffu, s0, 1);
        s0 += __shfl_xor_sync(0xffffffffu, s0, 2);
        s1 += __shfl_xor_sync(0xffffffffu, s1, 1);
        s1 += __shfl_xor_sync(0xffffffffu, s1, 2);
        if (t == 0) {
            spart[wm][wn * 64 + mi * 16 + g]     = s0;
            spart[wm][wn * 64 + mi * 16 + 8 + g] = s1;
        }
    }
    __syncthreads();
    if (tid < 128) {
        float v = spart[0][tid] + spart[1][tid] + spart[2][tid] + spart[3][tid];
        g_partial[(bx * 128 + tid) * MB + by] = v;   // transposed for tail1
    }
}

// ---------------------------------------------------------------------------
// tail1: dist[n] = mean of 16 contiguous partials; per-block min/max (16 blocks)
// ---------------------------------------------------------------------------
__global__ void tail1_kernel() {
    __shared__ float smx[16], smn[16];
    int n = blockIdx.x * 512 + threadIdx.x;
    const float4* p = (const float4*)(g_partial + n * MB);
    float4 v0 = p[0], v1 = p[1], v2 = p[2], v3 = p[3];
    float s = ((v0.x + v0.y) + (v0.z + v0.w)) + ((v1.x + v1.y) + (v1.z + v1.w))
            + ((v2.x + v2.y) + (v2.z + v2.w)) + ((v3.x + v3.y) + (v3.z + v3.w));
    float d = s * (1.0f / (float)Mm);
    g_dist[n] = d;
    float mx = d, mn = d;
#pragma unroll
    for (int o = 16; o > 0; o >>= 1) {
        mx = fmaxf(mx, __shfl_xor_sync(0xffffffffu, mx, o));
        mn = fminf(mn, __shfl_xor_sync(0xffffffffu, mn, o));
    }
    int wi = threadIdx.x >> 5;
    if ((threadIdx.x & 31) == 0) { smx[wi] = mx; smn[wi] = mn; }
    __syncthreads();
    if (threadIdx.x < 32) {
        mx = smx[threadIdx.x & 15]; mn = smn[threadIdx.x & 15];
#pragma unroll
        for (int o = 8; o > 0; o >>= 1) {
            mx = fmaxf(mx, __shfl_xor_sync(0xffffffffu, mx, o));
            mn = fminf(mn, __shfl_xor_sync(0xffffffffu, mn, o));
        }
        if (threadIdx.x == 0) g_mm[blockIdx.x] = make_float2(mx, mn);
    }
}

// ---------------------------------------------------------------------------
// tail2: off = global max + min over 16 block results; out = off - dist
// ---------------------------------------------------------------------------
__global__ void tail2_kernel(float* __restrict__ out) {
    float mx = -INFINITY, mn = INFINITY;
#pragma unroll
    for (int i = 0; i < 16; i++) {
        float2 v = __ldg(&g_mm[i]);
        mx = fmaxf(mx, v.x);
        mn = fminf(mn, v.y);
    }
    int n = blockIdx.x * 512 + threadIdx.x;
    out[n] = (mx + mn) - g_dist[n];
}

// ---------------------------------------------------------------------------
extern "C" void kernel_launch(void* const* d_in, const int* in_sizes, int n_in,
                              void* d_out, int out_size) {
    const float* samples = (const float*)d_in[0];
    const float* means   = (const float*)d_in[1];
    const float* stds    = (const float*)d_in[2];
    float* out = (float*)d_out;

    prep_kernel<<<1024, 256>>>(samples, means, stds);
    dim3 grid(Nn / 128, Mm / 128);
    kde_main<<<grid, 256>>>();
    tail1_kernel<<<Nn / 512, 512>>>();
    tail2_kernel<<<Nn / 512, 512>>>(out);
}